// round 1
// baseline (speedup 1.0000x reference)
#include <cuda_runtime.h>
#include <cuda_bf16.h>

// AttentionPooling: B=64, S=4096, D=256, fp32.
//   LN(x) over D -> Dense(1) score -> softmax over S -> out[b,d] = sum_s x * w_s
// Single pass over x via online softmax with split-chunk partials.

#define BDIM   64
#define SDIM   4096
#define DDIM   256
#define CHUNKS 32
#define RPC    (SDIM / CHUNKS)   /* 128 rows per block */
#define WARPS  8
#define NTHR   (WARPS * 32)
#define LN_EPS 1e-3f

// Split-softmax partial scratch (static device globals; no allocation).
__device__ float g_pacc[BDIM * CHUNKS * DDIM];   // 2 MB
__device__ float g_pm[BDIM * CHUNKS];
__device__ float g_pl[BDIM * CHUNKS];

__device__ __forceinline__ float warp_sum(float v) {
    #pragma unroll
    for (int o = 16; o > 0; o >>= 1) v += __shfl_xor_sync(0xffffffffu, v, o);
    return v;
}

__global__ __launch_bounds__(NTHR)
void ap_pass1(const float* __restrict__ x, const float* __restrict__ mask,
              const float* __restrict__ gamma, const float* __restrict__ beta,
              const float* __restrict__ w, const float* __restrict__ bias)
{
    const int b     = blockIdx.y;
    const int chunk = blockIdx.x;
    const int wid   = threadIdx.x >> 5;
    const int lid   = threadIdx.x & 31;

    // Per-lane parameter slices: d = lid*4 .. lid*4+3  and  128 + lid*4 ..
    const float4 gm0 = ((const float4*)gamma)[lid];
    const float4 gm1 = ((const float4*)gamma)[32 + lid];
    const float4 ww0 = ((const float4*)w)[lid];
    const float4 ww1 = ((const float4*)w)[32 + lid];
    const float4 bt0 = ((const float4*)beta)[lid];
    const float4 bt1 = ((const float4*)beta)[32 + lid];

    float gw0[4] = {gm0.x*ww0.x, gm0.y*ww0.y, gm0.z*ww0.z, gm0.w*ww0.w};
    float gw1[4] = {gm1.x*ww1.x, gm1.y*ww1.y, gm1.z*ww1.z, gm1.w*ww1.w};

    // Scalars: sum(gamma*w) and dot(beta, w)  (same on all lanes after reduce)
    float sgw = gw0[0]+gw0[1]+gw0[2]+gw0[3] + gw1[0]+gw1[1]+gw1[2]+gw1[3];
    float bw  = bt0.x*ww0.x + bt0.y*ww0.y + bt0.z*ww0.z + bt0.w*ww0.w
              + bt1.x*ww1.x + bt1.y*ww1.y + bt1.z*ww1.z + bt1.w*ww1.w;
    sgw = warp_sum(sgw);
    bw  = warp_sum(bw);
    const float bias0 = bias[0];
    const float score_c = bw + bias0;

    const float* xb = x + (size_t)b * SDIM * DDIM;
    const float* mb = mask + (size_t)b * SDIM;

    // Online softmax state (per warp, distributed acc across lanes)
    float m = -3.0e38f, l = 0.0f;
    float acc0[4] = {0.f, 0.f, 0.f, 0.f};
    float acc1[4] = {0.f, 0.f, 0.f, 0.f};

    const int s_begin = chunk * RPC;
    #pragma unroll 1
    for (int r = wid; r < RPC; r += WARPS) {
        const int s = s_begin + r;
        const float4* xr = (const float4*)(xb + (size_t)s * DDIM);
        const float4 x0 = xr[lid];
        const float4 x1 = xr[32 + lid];

        // Three row reductions: sum(x), sum(x^2), dot(x, gamma*w)
        float s1 = x0.x + x0.y + x0.z + x0.w + x1.x + x1.y + x1.z + x1.w;
        float s2 = x0.x*x0.x + x0.y*x0.y + x0.z*x0.z + x0.w*x0.w
                 + x1.x*x1.x + x1.y*x1.y + x1.z*x1.z + x1.w*x1.w;
        float sd = x0.x*gw0[0] + x0.y*gw0[1] + x0.z*gw0[2] + x0.w*gw0[3]
                 + x1.x*gw1[0] + x1.y*gw1[1] + x1.z*gw1[2] + x1.w*gw1[3];
        #pragma unroll
        for (int o = 16; o > 0; o >>= 1) {
            s1 += __shfl_xor_sync(0xffffffffu, s1, o);
            s2 += __shfl_xor_sync(0xffffffffu, s2, o);
            sd += __shfl_xor_sync(0xffffffffu, sd, o);
        }

        const float mu   = s1 * (1.0f / DDIM);
        const float var  = s2 * (1.0f / DDIM) - mu * mu;
        const float rstd = rsqrtf(var + LN_EPS);
        float score = rstd * (sd - mu * sgw) + score_c;
        score += (1.0f - mb[s]) * (-1.0e9f);

        const float mnew = fmaxf(m, score);
        const float cs = __expf(m - mnew);       // correction scale
        const float p  = __expf(score - mnew);
        l = l * cs + p;
        #pragma unroll
        for (int j = 0; j < 4; j++) acc0[j] = acc0[j] * cs;
        #pragma unroll
        for (int j = 0; j < 4; j++) acc1[j] = acc1[j] * cs;
        acc0[0] += p * x0.x; acc0[1] += p * x0.y; acc0[2] += p * x0.z; acc0[3] += p * x0.w;
        acc1[0] += p * x1.x; acc1[1] += p * x1.y; acc1[2] += p * x1.z; acc1[3] += p * x1.w;
        m = mnew;
    }

    // Combine the 8 warps of this block in shared memory.
    __shared__ float sm_acc[WARPS][DDIM];  // 8 KB
    __shared__ float sm_m[WARPS];
    __shared__ float sm_l[WARPS];

    #pragma unroll
    for (int j = 0; j < 4; j++) sm_acc[wid][lid * 4 + j]       = acc0[j];
    #pragma unroll
    for (int j = 0; j < 4; j++) sm_acc[wid][128 + lid * 4 + j] = acc1[j];
    if (lid == 0) { sm_m[wid] = m; sm_l[wid] = l; }
    __syncthreads();

    const int d = threadIdx.x;               // 0..255
    float M = -3.0e38f;
    #pragma unroll
    for (int ww = 0; ww < WARPS; ww++) M = fmaxf(M, sm_m[ww]);
    float L = 0.0f, A = 0.0f;
    #pragma unroll
    for (int ww = 0; ww < WARPS; ww++) {
        const float e = __expf(sm_m[ww] - M);
        L += e * sm_l[ww];
        A += e * sm_acc[ww][d];
    }
    const int pidx = b * CHUNKS + chunk;
    g_pacc[(size_t)pidx * DDIM + d] = A;
    if (threadIdx.x == 0) { g_pm[pidx] = M; g_pl[pidx] = L; }
}

__global__ __launch_bounds__(DDIM)
void ap_pass2(float* __restrict__ out)
{
    const int b = blockIdx.x;
    const int d = threadIdx.x;

    float M = -3.0e38f;
    #pragma unroll
    for (int i = 0; i < CHUNKS; i++) M = fmaxf(M, g_pm[b * CHUNKS + i]);
    float L = 0.0f, A = 0.0f;
    #pragma unroll
    for (int i = 0; i < CHUNKS; i++) {
        const float e = __expf(g_pm[b * CHUNKS + i] - M);
        L += e * g_pl[b * CHUNKS + i];
        A += e * g_pacc[((size_t)(b * CHUNKS + i)) * DDIM + d];
    }
    out[b * DDIM + d] = A / L;
}

extern "C" void kernel_launch(void* const* d_in, const int* in_sizes, int n_in,
                              void* d_out, int out_size)
{
    const float* x     = (const float*)d_in[0];
    const float* mask  = (const float*)d_in[1];
    const float* gamma = (const float*)d_in[2];
    const float* beta  = (const float*)d_in[3];
    const float* w     = (const float*)d_in[4];
    const float* bias  = (const float*)d_in[5];
    float* out = (float*)d_out;

    dim3 grid1(CHUNKS, BDIM);
    ap_pass1<<<grid1, NTHR>>>(x, mask, gamma, beta, w, bias);
    ap_pass2<<<BDIM, DDIM>>>(out);
}

// round 2
// speedup vs baseline: 1.3127x; 1.3127x over previous
#include <cuda_runtime.h>
#include <cuda_bf16.h>

// AttentionPooling: B=64, S=4096, D=256, fp32.
//   LN(x) over D -> Dense(1) score -> softmax over S -> out[b,d] = sum_s x_s * w_s
// Single fused kernel: one pass over x with online softmax, 4-row batching,
// split-chunk partials combined by the last-arriving block per batch.

#define BDIM   64
#define SDIM   4096
#define DDIM   256
#define CHUNKS 32
#define RPC    (SDIM / CHUNKS)   /* 128 rows per block */
#define WARPS  8
#define NTHR   (WARPS * 32)
#define RPW    (RPC / WARPS)     /* 16 rows per warp */
#define RB     4                 /* row batch */
#define LN_EPS 1e-3f

// Split-softmax partial scratch + completion counters (static device globals).
__device__ float g_pacc[BDIM * CHUNKS * DDIM];   // 2 MB
__device__ float g_pm[BDIM * CHUNKS];
__device__ float g_pl[BDIM * CHUNKS];
__device__ int   g_cnt[BDIM];                    // zero-init; self-resetting

__device__ __forceinline__ float warp_sum(float v) {
    #pragma unroll
    for (int o = 16; o > 0; o >>= 1) v += __shfl_xor_sync(0xffffffffu, v, o);
    return v;
}

__global__ __launch_bounds__(NTHR)
void ap_fused(const float* __restrict__ x, const float* __restrict__ mask,
              const float* __restrict__ gamma, const float* __restrict__ beta,
              const float* __restrict__ w, const float* __restrict__ bias,
              float* __restrict__ out)
{
    const int b     = blockIdx.y;
    const int chunk = blockIdx.x;
    const int wid   = threadIdx.x >> 5;
    const int lid   = threadIdx.x & 31;

    // Per-lane parameter slices: d = lid*4..lid*4+3 and 128+lid*4..
    const float4 gm0 = __ldg(((const float4*)gamma) + lid);
    const float4 gm1 = __ldg(((const float4*)gamma) + 32 + lid);
    const float4 ww0 = __ldg(((const float4*)w) + lid);
    const float4 ww1 = __ldg(((const float4*)w) + 32 + lid);
    const float4 bt0 = __ldg(((const float4*)beta) + lid);
    const float4 bt1 = __ldg(((const float4*)beta) + 32 + lid);

    const float gw0[4] = {gm0.x*ww0.x, gm0.y*ww0.y, gm0.z*ww0.z, gm0.w*ww0.w};
    const float gw1[4] = {gm1.x*ww1.x, gm1.y*ww1.y, gm1.z*ww1.z, gm1.w*ww1.w};

    float sgw = gw0[0]+gw0[1]+gw0[2]+gw0[3] + gw1[0]+gw1[1]+gw1[2]+gw1[3];
    float bw  = bt0.x*ww0.x + bt0.y*ww0.y + bt0.z*ww0.z + bt0.w*ww0.w
              + bt1.x*ww1.x + bt1.y*ww1.y + bt1.z*ww1.z + bt1.w*ww1.w;
    sgw = warp_sum(sgw);
    bw  = warp_sum(bw);
    const float score_c = bw + __ldg(bias);

    const float* xb = x + (size_t)b * SDIM * DDIM;
    const float* mb = mask + (size_t)b * SDIM;

    // Online softmax state (per warp; acc distributed across lanes)
    float m = -3.0e38f, l = 0.0f;
    float acc0[4] = {0.f, 0.f, 0.f, 0.f};
    float acc1[4] = {0.f, 0.f, 0.f, 0.f};

    const int row_base = chunk * RPC + wid * RPW;

    #pragma unroll 1
    for (int it = 0; it < RPW / RB; it++) {
        const int s0 = row_base + it * RB;

        // Load 4 rows (8 independent LDG.128 per lane)
        float4 xv0[RB], xv1[RB];
        #pragma unroll
        for (int k = 0; k < RB; k++) {
            const float4* xr = (const float4*)(xb + (size_t)(s0 + k) * DDIM);
            xv0[k] = __ldg(xr + lid);
            xv1[k] = __ldg(xr + 32 + lid);
        }

        // Per-row partials: sum(x), sum(x^2), dot(x, gamma*w)
        float p1[RB], p2[RB], pd[RB];
        #pragma unroll
        for (int k = 0; k < RB; k++) {
            const float4 a = xv0[k], c = xv1[k];
            p1[k] = a.x + a.y + a.z + a.w + c.x + c.y + c.z + c.w;
            p2[k] = a.x*a.x + a.y*a.y + a.z*a.z + a.w*a.w
                  + c.x*c.x + c.y*c.y + c.z*c.z + c.w*c.w;
            pd[k] = a.x*gw0[0] + a.y*gw0[1] + a.z*gw0[2] + a.w*gw0[3]
                  + c.x*gw1[0] + c.y*gw1[1] + c.z*gw1[2] + c.w*gw1[3];
        }
        // 12 concurrent butterfly chains
        #pragma unroll
        for (int o = 16; o > 0; o >>= 1) {
            #pragma unroll
            for (int k = 0; k < RB; k++) {
                p1[k] += __shfl_xor_sync(0xffffffffu, p1[k], o);
                p2[k] += __shfl_xor_sync(0xffffffffu, p2[k], o);
                pd[k] += __shfl_xor_sync(0xffffffffu, pd[k], o);
            }
        }

        const float4 mv = __ldg((const float4*)(mb + s0));
        const float mk[RB] = {mv.x, mv.y, mv.z, mv.w};

        float sc[RB];
        #pragma unroll
        for (int k = 0; k < RB; k++) {
            const float mu   = p1[k] * (1.0f / DDIM);
            const float var  = p2[k] * (1.0f / DDIM) - mu * mu;
            const float rstd = rsqrtf(var + LN_EPS);
            sc[k] = rstd * (pd[k] - mu * sgw) + score_c
                  + (1.0f - mk[k]) * (-1.0e9f);
        }

        // One rescale per 4 rows
        float mnew = m;
        #pragma unroll
        for (int k = 0; k < RB; k++) mnew = fmaxf(mnew, sc[k]);
        const float cs = __expf(m - mnew);
        float p[RB];
        float psum = 0.0f;
        #pragma unroll
        for (int k = 0; k < RB; k++) { p[k] = __expf(sc[k] - mnew); psum += p[k]; }
        l = l * cs + psum;
        m = mnew;

        #pragma unroll
        for (int j = 0; j < 4; j++) {
            float a0 = acc0[j] * cs;
            float a1 = acc1[j] * cs;
            a0 = fmaf(p[0], ((const float*)&xv0[0])[j], a0);
            a0 = fmaf(p[1], ((const float*)&xv0[1])[j], a0);
            a0 = fmaf(p[2], ((const float*)&xv0[2])[j], a0);
            a0 = fmaf(p[3], ((const float*)&xv0[3])[j], a0);
            a1 = fmaf(p[0], ((const float*)&xv1[0])[j], a1);
            a1 = fmaf(p[1], ((const float*)&xv1[1])[j], a1);
            a1 = fmaf(p[2], ((const float*)&xv1[2])[j], a1);
            a1 = fmaf(p[3], ((const float*)&xv1[3])[j], a1);
            acc0[j] = a0;
            acc1[j] = a1;
        }
    }

    // Combine the 8 warps of this block in shared memory.
    __shared__ float sm_acc[WARPS][DDIM];  // 8 KB
    __shared__ float sm_m[WARPS];
    __shared__ float sm_l[WARPS];

    #pragma unroll
    for (int j = 0; j < 4; j++) sm_acc[wid][lid * 4 + j]       = acc0[j];
    #pragma unroll
    for (int j = 0; j < 4; j++) sm_acc[wid][128 + lid * 4 + j] = acc1[j];
    if (lid == 0) { sm_m[wid] = m; sm_l[wid] = l; }
    __syncthreads();

    const int d = threadIdx.x;               // 0..255
    float M = -3.0e38f;
    #pragma unroll
    for (int ww = 0; ww < WARPS; ww++) M = fmaxf(M, sm_m[ww]);
    float L = 0.0f, A = 0.0f;
    #pragma unroll
    for (int ww = 0; ww < WARPS; ww++) {
        const float e = __expf(sm_m[ww] - M);
        L += e * sm_l[ww];
        A += e * sm_acc[ww][d];
    }
    const int pidx = b * CHUNKS + chunk;
    g_pacc[(size_t)pidx * DDIM + d] = A;
    if (threadIdx.x == 0) { g_pm[pidx] = M; g_pl[pidx] = L; }

    // --- Split-K style combine: last block for this batch does the reduction ---
    __threadfence();
    __shared__ int s_is_last;
    __syncthreads();
    if (threadIdx.x == 0) {
        const int old = atomicAdd(&g_cnt[b], 1);
        s_is_last = (old == CHUNKS - 1);
    }
    __syncthreads();

    if (s_is_last) {
        __threadfence();  // acquire: see all other blocks' partials
        float Mg = -3.0e38f;
        #pragma unroll
        for (int i = 0; i < CHUNKS; i++) Mg = fmaxf(Mg, g_pm[b * CHUNKS + i]);
        float Lg = 0.0f, Ag = 0.0f;
        #pragma unroll
        for (int i = 0; i < CHUNKS; i++) {
            const float e = __expf(g_pm[b * CHUNKS + i] - Mg);
            Lg += e * g_pl[b * CHUNKS + i];
            Ag += e * g_pacc[((size_t)(b * CHUNKS + i)) * DDIM + d];
        }
        out[b * DDIM + d] = Ag / Lg;
        __syncthreads();
        if (threadIdx.x == 0) g_cnt[b] = 0;   // reset for next graph replay
    }
}

extern "C" void kernel_launch(void* const* d_in, const int* in_sizes, int n_in,
                              void* d_out, int out_size)
{
    const float* x     = (const float*)d_in[0];
    const float* mask  = (const float*)d_in[1];
    const float* gamma = (const float*)d_in[2];
    const float* beta  = (const float*)d_in[3];
    const float* w     = (const float*)d_in[4];
    const float* bias  = (const float*)d_in[5];
    float* out = (float*)d_out;

    dim3 grid(CHUNKS, BDIM);
    ap_fused<<<grid, NTHR>>>(x, mask, gamma, beta, w, bias, out);
}

// round 3
// speedup vs baseline: 1.4018x; 1.0679x over previous
#include <cuda_runtime.h>
#include <cuda_bf16.h>

// AttentionPooling: B=64, S=4096, D=256, fp32.
//   LN(x) over D -> Dense(1) score -> softmax over S -> out[b,d] = sum_s x_s * w_s
// Single fused kernel, one pass over x: online softmax, 4-row batching,
// double-buffered (software-pipelined) loads so LDGs are always in flight,
// split-chunk partials combined by the last-arriving block per batch.

#define BDIM   64
#define SDIM   4096
#define DDIM   256
#define CHUNKS 32
#define RPC    (SDIM / CHUNKS)   /* 128 rows per block */
#define WARPS  8
#define NTHR   (WARPS * 32)
#define RPW    (RPC / WARPS)     /* 16 rows per warp */
#define RB     4                 /* row batch */
#define NIT    (RPW / RB)        /* 4 pipelined iterations */
#define LN_EPS 1e-3f

// Split-softmax partial scratch + completion counters (static device globals).
__device__ float g_pacc[BDIM * CHUNKS * DDIM];   // 2 MB
__device__ float g_pm[BDIM * CHUNKS];
__device__ float g_pl[BDIM * CHUNKS];
__device__ int   g_cnt[BDIM];                    // zero-init; self-resetting

__device__ __forceinline__ float warp_sum(float v) {
    #pragma unroll
    for (int o = 16; o > 0; o >>= 1) v += __shfl_xor_sync(0xffffffffu, v, o);
    return v;
}

__global__ __launch_bounds__(NTHR, 2)
void ap_fused(const float* __restrict__ x, const float* __restrict__ mask,
              const float* __restrict__ gamma, const float* __restrict__ beta,
              const float* __restrict__ w, const float* __restrict__ bias,
              float* __restrict__ out)
{
    const int b     = blockIdx.y;
    const int chunk = blockIdx.x;
    const int wid   = threadIdx.x >> 5;
    const int lid   = threadIdx.x & 31;

    // Per-lane parameter slices: d = lid*4..lid*4+3 and 128+lid*4..
    const float4 gm0 = __ldg(((const float4*)gamma) + lid);
    const float4 gm1 = __ldg(((const float4*)gamma) + 32 + lid);
    const float4 ww0 = __ldg(((const float4*)w) + lid);
    const float4 ww1 = __ldg(((const float4*)w) + 32 + lid);
    const float4 bt0 = __ldg(((const float4*)beta) + lid);
    const float4 bt1 = __ldg(((const float4*)beta) + 32 + lid);

    const float gw0[4] = {gm0.x*ww0.x, gm0.y*ww0.y, gm0.z*ww0.z, gm0.w*ww0.w};
    const float gw1[4] = {gm1.x*ww1.x, gm1.y*ww1.y, gm1.z*ww1.z, gm1.w*ww1.w};

    float sgw = gw0[0]+gw0[1]+gw0[2]+gw0[3] + gw1[0]+gw1[1]+gw1[2]+gw1[3];
    float bw  = bt0.x*ww0.x + bt0.y*ww0.y + bt0.z*ww0.z + bt0.w*ww0.w
              + bt1.x*ww1.x + bt1.y*ww1.y + bt1.z*ww1.z + bt1.w*ww1.w;
    sgw = warp_sum(sgw);
    bw  = warp_sum(bw);
    const float score_c = bw + __ldg(bias);

    const float* xb = x + (size_t)b * SDIM * DDIM;
    const float* mb = mask + (size_t)b * SDIM;

    // Online softmax state (per warp; acc distributed across lanes)
    float m = -3.0e38f, l = 0.0f;
    float acc0[4] = {0.f, 0.f, 0.f, 0.f};
    float acc1[4] = {0.f, 0.f, 0.f, 0.f};

    const int row_base = chunk * RPC + wid * RPW;

    // Double-buffered row data: [buffer][row] low/high halves + mask vec.
    float4 xv0[2][RB], xv1[2][RB];
    float4 mbuf[2];

    // Prologue: load iteration 0 (streaming loads: x is read exactly once).
    #pragma unroll
    for (int k = 0; k < RB; k++) {
        const float4* xr = (const float4*)(xb + (size_t)(row_base + k) * DDIM);
        xv0[0][k] = __ldcs(xr + lid);
        xv1[0][k] = __ldcs(xr + 32 + lid);
    }
    mbuf[0] = __ldg((const float4*)(mb + row_base));

    #pragma unroll
    for (int it = 0; it < NIT; it++) {
        const int cur = it & 1;
        const int nxt = cur ^ 1;

        // Prefetch next iteration's rows while this one computes.
        if (it + 1 < NIT) {
            const int sN = row_base + (it + 1) * RB;
            #pragma unroll
            for (int k = 0; k < RB; k++) {
                const float4* xr = (const float4*)(xb + (size_t)(sN + k) * DDIM);
                xv0[nxt][k] = __ldcs(xr + lid);
                xv1[nxt][k] = __ldcs(xr + 32 + lid);
            }
            mbuf[nxt] = __ldg((const float4*)(mb + sN));
        }

        // Per-row partials: sum(x), sum(x^2), dot(x, gamma*w)
        float p1[RB], p2[RB], pd[RB];
        #pragma unroll
        for (int k = 0; k < RB; k++) {
            const float4 a = xv0[cur][k], c = xv1[cur][k];
            p1[k] = a.x + a.y + a.z + a.w + c.x + c.y + c.z + c.w;
            p2[k] = a.x*a.x + a.y*a.y + a.z*a.z + a.w*a.w
                  + c.x*c.x + c.y*c.y + c.z*c.z + c.w*c.w;
            pd[k] = a.x*gw0[0] + a.y*gw0[1] + a.z*gw0[2] + a.w*gw0[3]
                  + c.x*gw1[0] + c.y*gw1[1] + c.z*gw1[2] + c.w*gw1[3];
        }
        // 12 concurrent butterfly chains
        #pragma unroll
        for (int o = 16; o > 0; o >>= 1) {
            #pragma unroll
            for (int k = 0; k < RB; k++) {
                p1[k] += __shfl_xor_sync(0xffffffffu, p1[k], o);
                p2[k] += __shfl_xor_sync(0xffffffffu, p2[k], o);
                pd[k] += __shfl_xor_sync(0xffffffffu, pd[k], o);
            }
        }

        const float mk[RB] = {mbuf[cur].x, mbuf[cur].y, mbuf[cur].z, mbuf[cur].w};

        float sc[RB];
        #pragma unroll
        for (int k = 0; k < RB; k++) {
            const float mu   = p1[k] * (1.0f / DDIM);
            const float var  = p2[k] * (1.0f / DDIM) - mu * mu;
            const float rstd = rsqrtf(var + LN_EPS);
            sc[k] = rstd * (pd[k] - mu * sgw) + score_c
                  + (1.0f - mk[k]) * (-1.0e9f);
        }

        // One rescale per 4 rows
        float mnew = m;
        #pragma unroll
        for (int k = 0; k < RB; k++) mnew = fmaxf(mnew, sc[k]);
        const float cs = __expf(m - mnew);
        float p[RB];
        float psum = 0.0f;
        #pragma unroll
        for (int k = 0; k < RB; k++) { p[k] = __expf(sc[k] - mnew); psum += p[k]; }
        l = l * cs + psum;
        m = mnew;

        #pragma unroll
        for (int j = 0; j < 4; j++) {
            float a0 = acc0[j] * cs;
            float a1 = acc1[j] * cs;
            a0 = fmaf(p[0], ((const float*)&xv0[cur][0])[j], a0);
            a0 = fmaf(p[1], ((const float*)&xv0[cur][1])[j], a0);
            a0 = fmaf(p[2], ((const float*)&xv0[cur][2])[j], a0);
            a0 = fmaf(p[3], ((const float*)&xv0[cur][3])[j], a0);
            a1 = fmaf(p[0], ((const float*)&xv1[cur][0])[j], a1);
            a1 = fmaf(p[1], ((const float*)&xv1[cur][1])[j], a1);
            a1 = fmaf(p[2], ((const float*)&xv1[cur][2])[j], a1);
            a1 = fmaf(p[3], ((const float*)&xv1[cur][3])[j], a1);
            acc0[j] = a0;
            acc1[j] = a1;
        }
    }

    // Combine the 8 warps of this block in shared memory.
    __shared__ float sm_acc[WARPS][DDIM];  // 8 KB
    __shared__ float sm_m[WARPS];
    __shared__ float sm_l[WARPS];

    #pragma unroll
    for (int j = 0; j < 4; j++) sm_acc[wid][lid * 4 + j]       = acc0[j];
    #pragma unroll
    for (int j = 0; j < 4; j++) sm_acc[wid][128 + lid * 4 + j] = acc1[j];
    if (lid == 0) { sm_m[wid] = m; sm_l[wid] = l; }
    __syncthreads();

    const int d = threadIdx.x;               // 0..255
    float M = -3.0e38f;
    #pragma unroll
    for (int ww = 0; ww < WARPS; ww++) M = fmaxf(M, sm_m[ww]);
    float L = 0.0f, A = 0.0f;
    #pragma unroll
    for (int ww = 0; ww < WARPS; ww++) {
        const float e = __expf(sm_m[ww] - M);
        L += e * sm_l[ww];
        A += e * sm_acc[ww][d];
    }
    const int pidx = b * CHUNKS + chunk;
    g_pacc[(size_t)pidx * DDIM + d] = A;
    if (threadIdx.x == 0) { g_pm[pidx] = M; g_pl[pidx] = L; }

    // --- Split-K style combine: last block for this batch does the reduction ---
    __threadfence();
    __shared__ int s_is_last;
    __syncthreads();
    if (threadIdx.x == 0) {
        const int old = atomicAdd(&g_cnt[b], 1);
        s_is_last = (old == CHUNKS - 1);
    }
    __syncthreads();

    if (s_is_last) {
        __threadfence();  // acquire: see all other blocks' partials
        float Mg = -3.0e38f;
        #pragma unroll
        for (int i = 0; i < CHUNKS; i++) Mg = fmaxf(Mg, g_pm[b * CHUNKS + i]);
        float Lg = 0.0f, Ag = 0.0f;
        #pragma unroll
        for (int i = 0; i < CHUNKS; i++) {
            const float e = __expf(g_pm[b * CHUNKS + i] - Mg);
            Lg += e * g_pl[b * CHUNKS + i];
            Ag += e * g_pacc[((size_t)(b * CHUNKS + i)) * DDIM + d];
        }
        out[b * DDIM + d] = Ag / Lg;
        __syncthreads();
        if (threadIdx.x == 0) g_cnt[b] = 0;   // reset for next graph replay
    }
}

extern "C" void kernel_launch(void* const* d_in, const int* in_sizes, int n_in,
                              void* d_out, int out_size)
{
    const float* x     = (const float*)d_in[0];
    const float* mask  = (const float*)d_in[1];
    const float* gamma = (const float*)d_in[2];
    const float* beta  = (const float*)d_in[3];
    const float* w     = (const float*)d_in[4];
    const float* bias  = (const float*)d_in[5];
    float* out = (float*)d_out;

    dim3 grid(CHUNKS, BDIM);
    ap_fused<<<grid, NTHR>>>(x, mask, gamma, beta, w, bias, out);
}